// round 13
// baseline (speedup 1.0000x reference)
#include <cuda_runtime.h>
#include <cuda_bf16.h>
#include <math.h>

// Problem dims (fixed by the reference)
#define BD 64
#define SD 128
#define ED 1024
#define HD_ 8
#define DH 128
#define KPD 32
#define MTOT (BD*SD)   // 8192
#define NKV 512

// Scratch (device globals — allocation-free rule)
__device__ __nv_bfloat16 g_xh  [MTOT*ED];
__device__ __nv_bfloat16 g_xl  [MTOT*ED];
__device__ __nv_bfloat16 g_Woh [ED*ED];
__device__ __nv_bfloat16 g_Wol [ED*ED];
__device__ __nv_bfloat16 g_Wkvph[NKV*ED];
__device__ __nv_bfloat16 g_Wkvpl[NKV*ED];
__device__ float         g_bkvp[NKV];
__device__ __nv_bfloat16 g_WqTh[ED*ED];
__device__ __nv_bfloat16 g_WqTl[ED*ED];
__device__ float         g_KV  [MTOT*NKV];
__device__ __nv_bfloat16 g_Kpth[16384*128];
__device__ __nv_bfloat16 g_Kptl[16384*128];
__device__ __nv_bfloat16 g_Vpth[16384*128];
__device__ __nv_bfloat16 g_Vptl[16384*128];
__device__ float         g_c   [BD*256];
__device__ __nv_bfloat16 g_Gh  [16384*1024];
__device__ __nv_bfloat16 g_Gl  [16384*1024];
__device__ __nv_bfloat16 g_ZTh [8*1024*2048];
__device__ __nv_bfloat16 g_ZTl [8*1024*2048];
__device__ __nv_bfloat16 g_attnh[MTOT*256];
__device__ __nv_bfloat16 g_attnl[MTOT*256];

// ---------------------------------------------------------------------------
// helpers
// ---------------------------------------------------------------------------
__device__ __forceinline__ unsigned smem_u32(const void* p) {
    unsigned a;
    asm("{ .reg .u64 t; cvta.to.shared.u64 t, %1; cvt.u32.u64 %0, t; }"
        : "=r"(a) : "l"(p));
    return a;
}
__device__ __forceinline__ void cp16(unsigned dst, const void* src) {
    asm volatile("cp.async.cg.shared.global [%0], [%1], 16;\n"
                 :: "r"(dst), "l"(src));
}
__device__ __forceinline__ void ldsm_x4(unsigned& r0, unsigned& r1,
                                        unsigned& r2, unsigned& r3, unsigned a) {
    asm volatile("ldmatrix.sync.aligned.m8n8.x4.shared.b16 {%0,%1,%2,%3}, [%4];\n"
                 : "=r"(r0), "=r"(r1), "=r"(r2), "=r"(r3) : "r"(a));
}
__device__ __forceinline__ void mma_bf16(
    float& c0, float& c1, float& c2, float& c3,
    unsigned a0, unsigned a1, unsigned a2, unsigned a3,
    unsigned b0, unsigned b1)
{
    asm volatile(
        "mma.sync.aligned.m16n8k16.row.col.f32.bf16.bf16.f32 "
        "{%0,%1,%2,%3}, {%4,%5,%6,%7}, {%8,%9}, {%0,%1,%2,%3};\n"
        : "+f"(c0), "+f"(c1), "+f"(c2), "+f"(c3)
        : "r"(a0), "r"(a1), "r"(a2), "r"(a3), "r"(b0), "r"(b1));
}
__device__ __forceinline__ void split1(float x, __nv_bfloat16& h, __nv_bfloat16& l) {
    h = __float2bfloat16_rn(x);
    l = __float2bfloat16_rn(x - __bfloat162float(h));
}

// ---------------------------------------------------------------------------
// fp32 -> bf16 hi/lo split
// ---------------------------------------------------------------------------
__global__ void __launch_bounds__(256) split_kernel(
    const float4* __restrict__ in, uint2* __restrict__ hi,
    uint2* __restrict__ lo, int n4)
{
    int i = blockIdx.x * blockDim.x + threadIdx.x;
    if (i >= n4) return;
    float4 v = in[i];
    __nv_bfloat16 h0,l0,h1,l1,h2,l2,h3,l3;
    split1(v.x,h0,l0); split1(v.y,h1,l1); split1(v.z,h2,l2); split1(v.w,h3,l3);
    __nv_bfloat162 ha(h0,h1), hb(h2,h3), la(l0,l1), lb(l2,l3);
    hi[i] = make_uint2(*(unsigned*)&ha, *(unsigned*)&hb);
    lo[i] = make_uint2(*(unsigned*)&la, *(unsigned*)&lb);
}

// ---------------------------------------------------------------------------
// Fold P into Wk / Wv; outputs bf16 hi/lo weights + fp32 bias
// ---------------------------------------------------------------------------
__global__ void __launch_bounds__(256) fold_kernel(
    const float* __restrict__ Wk, const float* __restrict__ bk,
    const float* __restrict__ Wv, const float* __restrict__ bv,
    const float* __restrict__ P,
    __nv_bfloat16* __restrict__ Wph, __nv_bfloat16* __restrict__ Wpl,
    float* __restrict__ bkvp)
{
    const int blk = blockIdx.x;
    const int kv = blk >> 3, h = blk & 7;
    const float* Wsrc = kv ? Wv : Wk;
    const float* bsrc = kv ? bv : bk;

    __shared__ float Ps[128][32];
    const int tid = threadIdx.x;
#pragma unroll
    for (int u = 0; u < 16; u++) {
        int e = tid + 256 * u;
        Ps[e >> 5][e & 31] = P[e];
    }
    __syncthreads();

    if (tid < 32) {
        float s = 0.f;
#pragma unroll 4
        for (int d = 0; d < 128; d++) s = fmaf(Ps[d][tid], bsrc[h * 128 + d], s);
        bkvp[kv * 256 + h * 32 + tid] = s;
    }

    for (int fc = 0; fc < 4; fc++) {
        const int f = fc * 256 + tid;
        float acc[32];
#pragma unroll
        for (int i = 0; i < 32; i++) acc[i] = 0.f;
        for (int d = 0; d < 128; d++) {
            float w = Wsrc[(size_t)(h * 128 + d) * ED + f];
#pragma unroll
            for (int i = 0; i < 32; i++) acc[i] = fmaf(Ps[d][i], w, acc[i]);
        }
#pragma unroll
        for (int i = 0; i < 32; i++) {
            __nv_bfloat16 hh, ll;
            split1(acc[i], hh, ll);
            size_t idx = (size_t)(kv * 256 + h * 32 + i) * ED + f;
            Wph[idx] = hh; Wpl[idx] = ll;
        }
    }
}

// ---------------------------------------------------------------------------
// Wq transpose -> bf16 hi/lo  WqT[(h*1024+e)*128 + t]
// ---------------------------------------------------------------------------
__global__ void __launch_bounds__(256) wq_trans(
    const float* __restrict__ Wq,
    __nv_bfloat16* __restrict__ Th, __nv_bfloat16* __restrict__ Tl)
{
    __shared__ float tile[32][33];
    const int h  = blockIdx.z;
    const int e0 = blockIdx.x * 32;
    const int t0 = blockIdx.y * 32;
    const int tx = threadIdx.x & 31;
    const int ty = threadIdx.x >> 5;
#pragma unroll
    for (int r = 0; r < 4; r++) {
        int tl = ty + r * 8;
        tile[tl][tx] = Wq[(size_t)(h * 128 + t0 + tl) * ED + e0 + tx];
    }
    __syncthreads();
#pragma unroll
    for (int r = 0; r < 4; r++) {
        int el = ty + r * 8;
        __nv_bfloat16 hh, ll;
        split1(tile[tx][el], hh, ll);
        size_t idx = (size_t)(h * 1024 + e0 + el) * 128 + t0 + tx;
        Th[idx] = hh; Tl[idx] = ll;
    }
}

// ---------------------------------------------------------------------------
// Transpose KVp -> Kpt/Vpt [h][b][j][t], bf16 hi/lo
// ---------------------------------------------------------------------------
__global__ void __launch_bounds__(256) trans_kv(
    const float* __restrict__ KVp,
    __nv_bfloat16* __restrict__ Kh, __nv_bfloat16* __restrict__ Kl,
    __nv_bfloat16* __restrict__ Vh, __nv_bfloat16* __restrict__ Vl)
{
    __shared__ float tile[32][129];
    const int cc = blockIdx.x;
    const int b  = blockIdx.y;
    const int tid = threadIdx.x;
#pragma unroll
    for (int u = 0; u < 16; u++) {
        int idx = tid + 256 * u;
        int t = idx >> 5, c = idx & 31;
        tile[c][t] = KVp[((size_t)b * 128 + t) * NKV + cc * 32 + c];
    }
    __syncthreads();
#pragma unroll
    for (int u = 0; u < 16; u++) {
        int idx = tid + 256 * u;
        int c = idx >> 7, t = idx & 127;
        int col = cc * 32 + c;
        __nv_bfloat16 hh, ll;
        split1(tile[c][t], hh, ll);
        if (col < 256) {
            int h = col >> 5, j = col & 31;
            size_t o = ((size_t)(h * 64 + b) * 32 + j) * 128 + t;
            Kh[o] = hh; Kl[o] = ll;
        } else {
            int c2 = col - 256;
            int h = c2 >> 5, j = c2 & 31;
            size_t o = ((size_t)(h * 64 + b) * 32 + j) * 128 + t;
            Vh[o] = hh; Vl[o] = ll;
        }
    }
}

// ---------------------------------------------------------------------------
// c[b][h*32+j] = sum_t Kpt[h,b,j,t] * bq[h*128+t]   (reads hi+lo)
// ---------------------------------------------------------------------------
__global__ void __launch_bounds__(256) c_kernel(
    const __nv_bfloat16* __restrict__ Kh, const __nv_bfloat16* __restrict__ Kl,
    const float* __restrict__ bq, float* __restrict__ cvec)
{
    const int b = blockIdx.x, hj = threadIdx.x;
    const int h = hj >> 5, j = hj & 31;
    const size_t base = ((size_t)(h * 64 + b) * 32 + j) * 128;
    const float* bqh = bq + h * 128;
    float s = 0.f;
#pragma unroll 4
    for (int t = 0; t < 128; t++)
        s = fmaf(__bfloat162float(Kh[base + t]) + __bfloat162float(Kl[base + t]),
                 __ldg(bqh + t), s);
    cvec[b * 256 + hj] = s;
}

// ---------------------------------------------------------------------------
// Unified pipelined GEMM core, bf16x3 emulation (round-8 structure).
// MODE 0: KVp = x @ Wkvp^T + bkvp            (K=1024, fp32 out, ldc 512)
// MODE 1: G[z] = Kpt_z @ WqT_z^T             (K=128,  bf16 hi/lo out, ldc 1024)
// MODE 2: ZT[z] = Wo(:, z*128:+128) @ Vpt_z^T (K=128, bf16 hi/lo out, ldc 2048)
// MODE 3: attn = softmax((x@G^T + c)*scale)  (K=1024, bf16 hi/lo out, ldc 256)
// MODE 4: out = attn @ ZT + bo               (K=256,  fp32 out, ldc 1024)
// ---------------------------------------------------------------------------
#define AROW 80
#define TILE_T (128*AROW)
#define BUF_T (4*TILE_T)     // 40960
#define GSMEM (2*BUF_T)      // 81920
#define GSMEM4 (4*BUF_T)     // 163840 (K=128 full prefetch)

template<int MODE>
__device__ __forceinline__ void stage_g5(
    unsigned dbase, int tid, int bm, int bn, int z, int b, int k0,
    const __nv_bfloat16* __restrict__ Ah, const __nv_bfloat16* __restrict__ Al,
    const __nv_bfloat16* __restrict__ Bh, const __nv_bfloat16* __restrict__ Bl)
{
#pragma unroll
    for (int idx = tid; idx < 512; idx += 256) {
        int row = idx >> 2, c16 = idx & 3;
        size_t off;
        if (MODE == 0 || MODE == 3)
            off = (size_t)(bm + row) * 1024 + k0 + c16 * 8;
        else if (MODE == 1)
            off = ((size_t)z * 2048 + bm + row) * 128 + k0 + c16 * 8;
        else if (MODE == 2)
            off = (size_t)(bm + row) * 1024 + z * 128 + k0 + c16 * 8;
        else
            off = (size_t)(bm + row) * 256 + k0 + c16 * 8;
        unsigned d = dbase + row * AROW + c16 * 16;
        cp16(d, Ah + off);
        cp16(d + TILE_T, Al + off);
    }
#pragma unroll
    for (int idx = tid; idx < 512; idx += 256) {
        int row = idx >> 2, c16 = idx & 3;
        size_t off;
        if (MODE == 0)
            off = (size_t)(bn + row) * 1024 + k0 + c16 * 8;
        else if (MODE == 1)
            off = ((size_t)z * 1024 + bn + row) * 128 + k0 + c16 * 8;
        else if (MODE == 2)
            off = ((size_t)z * 2048 + bn + row) * 128 + k0 + c16 * 8;
        else if (MODE == 3) {
            int nc = bn + row;
            off = ((size_t)(nc >> 5) * 2048 + b * 32 + (nc & 31)) * 1024 + k0 + c16 * 8;
        } else {
            int kc = k0 >> 5;
            off = (size_t)kc * (1024 * 2048) + (size_t)(bn + row) * 2048 + b * 32 + c16 * 8;
        }
        unsigned d = dbase + 2 * TILE_T + row * AROW + c16 * 16;
        cp16(d, Bh + off);
        cp16(d + TILE_T, Bl + off);
    }
}

// MMA body for one 32-K chunk resident in buffer at `bAh`
__device__ __forceinline__ void mma_chunk(
    unsigned bAh, int wm, int wn, int lr, int lc, float acc[4][4][4])
{
    const unsigned bAl = bAh + TILE_T;
    const unsigned bBh = bAh + 2 * TILE_T;
    const unsigned bBl = bBh + TILE_T;
#pragma unroll
    for (int kk = 0; kk < 2; kk++) {
        const int kb = kk * 32 + lc;
        unsigned bfh[4][2], bfl[4][2];
#pragma unroll
        for (int np = 0; np < 2; np++) {
            const int n0 = wn * 32 + np * 16;
            unsigned r0, r1, r2, r3;
            ldsm_x4(r0, r1, r2, r3, bBh + (n0 + lr) * AROW + kb);
            bfh[np*2][0] = r0; bfh[np*2+1][0] = r1;
            bfh[np*2][1] = r2; bfh[np*2+1][1] = r3;
            ldsm_x4(r0, r1, r2, r3, bBl + (n0 + lr) * AROW + kb);
            bfl[np*2][0] = r0; bfl[np*2+1][0] = r1;
            bfl[np*2][1] = r2; bfl[np*2+1][1] = r3;
        }
#pragma unroll
        for (int mt = 0; mt < 4; mt++) {
            const int m0 = wm * 64 + mt * 16;
            unsigned aH[4], aL[4];
            ldsm_x4(aH[0], aH[1], aH[2], aH[3], bAh + (m0 + lr) * AROW + kb);
            ldsm_x4(aL[0], aL[1], aL[2], aL[3], bAl + (m0 + lr) * AROW + kb);
#pragma unroll
            for (int nt = 0; nt < 4; nt++) {
                mma_bf16(acc[mt][nt][0], acc[mt][nt][1],
                         acc[mt][nt][2], acc[mt][nt][3],
                         aH[0], aH[1], aH[2], aH[3],
                         bfh[nt][0], bfh[nt][1]);
                mma_bf16(acc[mt][nt][0], acc[mt][nt][1],
                         acc[mt][nt][2], acc[mt][nt][3],
                         aH[0], aH[1], aH[2], aH[3],
                         bfl[nt][0], bfl[nt][1]);
                mma_bf16(acc[mt][nt][0], acc[mt][nt][1],
                         acc[mt][nt][2], acc[mt][nt][3],
                         aL[0], aL[1], aL[2], aL[3],
                         bfh[nt][0], bfh[nt][1]);
            }
        }
    }
}

template<int MODE>
__global__ void __launch_bounds__(256, 2) g5(
    const __nv_bfloat16* __restrict__ Ah, const __nv_bfloat16* __restrict__ Al,
    const __nv_bfloat16* __restrict__ Bh, const __nv_bfloat16* __restrict__ Bl,
    const float* __restrict__ bias, const float* __restrict__ cvec,
    float* __restrict__ Cf,
    __nv_bfloat16* __restrict__ Ch, __nv_bfloat16* __restrict__ Cl)
{
    constexpr int KTOT = (MODE == 4) ? 256 : 1024;
    constexpr int NS   = KTOT / 32;

    extern __shared__ char smem[];
    const unsigned sbase = smem_u32(smem);

    const int tid  = threadIdx.x;
    const int lane = tid & 31;
    const int w    = tid >> 5;
    const int wm   = w >> 2, wn = w & 3;
    const int gid  = lane >> 2, tig = lane & 3;
    const int lr   = lane & 15;
    const int lc   = (lane >> 4) * 16;

    const int bm = blockIdx.y * 128;
    const int bn = blockIdx.x * 128;
    const int b  = blockIdx.y;

    float acc[4][4][4];
#pragma unroll
    for (int mt = 0; mt < 4; mt++)
#pragma unroll
        for (int nt = 0; nt < 4; nt++)
#pragma unroll
            for (int i = 0; i < 4; i++) acc[mt][nt][i] = 0.f;

    stage_g5<MODE>(sbase, tid, bm, bn, 0, b, 0, Ah, Al, Bh, Bl);
    asm volatile("cp.async.commit_group;\n");

    int buf = 0;
    for (int s = 0; s < NS; s++) {
        if (s + 1 < NS) {
            stage_g5<MODE>(sbase + (buf ^ 1) * BUF_T, tid, bm, bn, 0, b,
                           (s + 1) * 32, Ah, Al, Bh, Bl);
            asm volatile("cp.async.commit_group;\n");
            asm volatile("cp.async.wait_group 1;\n");
        } else {
            asm volatile("cp.async.wait_group 0;\n");
        }
        __syncthreads();
        mma_chunk(sbase + buf * BUF_T, wm, wn, lr, lc, acc);
        __syncthreads();
        buf ^= 1;
    }

    // ------------------ epilogues ------------------
    if (MODE == 0 || MODE == 4) {
        const int ldc = (MODE == 0) ? 512 : 1024;
        const int rb  = (MODE == 0) ? bm : b * 128;
#pragma unroll
        for (int nt = 0; nt < 4; nt++) {
            int col = bn + wn * 32 + nt * 8 + tig * 2;
            float bb0 = __ldg(bias + col), bb1 = __ldg(bias + col + 1);
#pragma unroll
            for (int mt = 0; mt < 4; mt++) {
                int row = rb + wm * 64 + mt * 16 + gid;
                *(float2*)(Cf + (size_t)row * ldc + col) =
                    make_float2(acc[mt][nt][0] + bb0, acc[mt][nt][1] + bb1);
                *(float2*)(Cf + (size_t)(row + 8) * ldc + col) =
                    make_float2(acc[mt][nt][2] + bb0, acc[mt][nt][3] + bb1);
            }
        }
    } else {   // MODE 3: +c, scale, softmax per (row, 32-col h-group), bf16 hi/lo out
        const float scale = 0.08838834764831845f;
        float cA[4], cB[4];
#pragma unroll
        for (int nt = 0; nt < 4; nt++) {
            int col = bn + wn * 32 + nt * 8 + tig * 2;
            cA[nt] = __ldg(cvec + b * 256 + col);
            cB[nt] = __ldg(cvec + b * 256 + col + 1);
        }
#pragma unroll
        for (int mt = 0; mt < 4; mt++)
#pragma unroll
            for (int nt = 0; nt < 4; nt++) {
                acc[mt][nt][0] = (acc[mt][nt][0] + cA[nt]) * scale;
                acc[mt][nt][1] = (acc[mt][nt][1] + cB[nt]) * scale;
                acc[mt][nt][2] = (acc[mt][nt][2] + cA[nt]) * scale;
                acc[mt][nt][3] = (acc[mt][nt][3] + cB[nt]) * scale;
            }
#pragma unroll
        for (int mt = 0; mt < 4; mt++) {
            float m0 = -1e30f, m1 = -1e30f;
#pragma unroll
            for (int nt = 0; nt < 4; nt++) {
                m0 = fmaxf(m0, fmaxf(acc[mt][nt][0], acc[mt][nt][1]));
                m1 = fmaxf(m1, fmaxf(acc[mt][nt][2], acc[mt][nt][3]));
            }
            m0 = fmaxf(m0, __shfl_xor_sync(0xffffffffu, m0, 1));
            m0 = fmaxf(m0, __shfl_xor_sync(0xffffffffu, m0, 2));
            m1 = fmaxf(m1, __shfl_xor_sync(0xffffffffu, m1, 1));
            m1 = fmaxf(m1, __shfl_xor_sync(0xffffffffu, m1, 2));
            float s0 = 0.f, s1 = 0.f;
#pragma unroll
            for (int nt = 0; nt < 4; nt++) {
                acc[mt][nt][0] = expf(acc[mt][nt][0] - m0);
                acc[mt][nt][1] = expf(acc[mt][nt][1] - m0);
                acc[mt][nt][2] = expf(acc[mt][nt][2] - m1);
                acc[mt][nt][3] = expf(acc[mt][nt][3] - m1);
                s0 += acc[mt][nt][0] + acc[mt][nt][1];
                s1 += acc[mt][nt][2] + acc[mt][nt][3];
            }
            s0 += __shfl_xor_sync(0xffffffffu, s0, 1);
            s0 += __shfl_xor_sync(0xffffffffu, s0, 2);
            s1 += __shfl_xor_sync(0xffffffffu, s1, 1);
            s1 += __shfl_xor_sync(0xffffffffu, s1, 2);
            float i0 = 1.f / s0, i1 = 1.f / s1;
#pragma unroll
            for (int nt = 0; nt < 4; nt++) {
                acc[mt][nt][0] *= i0; acc[mt][nt][1] *= i0;
                acc[mt][nt][2] *= i1; acc[mt][nt][3] *= i1;
            }
        }
#pragma unroll
        for (int nt = 0; nt < 4; nt++) {
            int col = bn + wn * 32 + nt * 8 + tig * 2;
#pragma unroll
            for (int mt = 0; mt < 4; mt++) {
                size_t row = (size_t)bm + wm * 64 + mt * 16 + gid;
                __nv_bfloat16 h0, l0, h1, l1;
                split1(acc[mt][nt][0], h0, l0); split1(acc[mt][nt][1], h1, l1);
                *(__nv_bfloat162*)(Ch + row * 256 + col) = __nv_bfloat162(h0, h1);
                *(__nv_bfloat162*)(Cl + row * 256 + col) = __nv_bfloat162(l0, l1);
                split1(acc[mt][nt][2], h0, l0); split1(acc[mt][nt][3], h1, l1);
                *(__nv_bfloat162*)(Ch + (row + 8) * 256 + col) = __nv_bfloat162(h0, h1);
                *(__nv_bfloat162*)(Cl + (row + 8) * 256 + col) = __nv_bfloat162(l0, l1);
            }
        }
    }
}

// ---------------------------------------------------------------------------
// K=128 GEMM with full-K prefetch (4 buffers, occ 1): MODE 1 (G) / MODE 2 (ZT)
// ---------------------------------------------------------------------------
template<int MODE>
__global__ void __launch_bounds__(256, 1) g5k128(
    const __nv_bfloat16* __restrict__ Ah, const __nv_bfloat16* __restrict__ Al,
    const __nv_bfloat16* __restrict__ Bh, const __nv_bfloat16* __restrict__ Bl,
    __nv_bfloat16* __restrict__ Ch, __nv_bfloat16* __restrict__ Cl)
{
    extern __shared__ char smem[];
    const unsigned sbase = smem_u32(smem);

    const int tid  = threadIdx.x;
    const int lane = tid & 31;
    const int w    = tid >> 5;
    const int wm   = w >> 2, wn = w & 3;
    const int gid  = lane >> 2, tig = lane & 3;
    const int lr   = lane & 15;
    const int lc   = (lane >> 4) * 16;

    const int bm = blockIdx.y * 128;
    const int bn = blockIdx.x * 128;
    const int z  = blockIdx.z;

    float acc[4][4][4];
#pragma unroll
    for (int mt = 0; mt < 4; mt++)
#pragma unroll
        for (int nt = 0; nt < 4; nt++)
#pragma unroll
            for (int i = 0; i < 4; i++) acc[mt][nt][i] = 0.f;

    // prefetch ALL four 32-K chunks into 4 distinct buffers
#pragma unroll
    for (int c = 0; c < 4; c++) {
        stage_g5<MODE>(sbase + c * BUF_T, tid, bm, bn, z, 0, c * 32, Ah, Al, Bh, Bl);
        asm volatile("cp.async.commit_group;\n");
    }

    asm volatile("cp.async.wait_group 3;\n"); __syncthreads();
    mma_chunk(sbase,             wm, wn, lr, lc, acc);
    asm volatile("cp.async.wait_group 2;\n"); __syncthreads();
    mma_chunk(sbase + BUF_T,     wm, wn, lr, lc, acc);
    asm volatile("cp.async.wait_group 1;\n"); __syncthreads();
    mma_chunk(sbase + 2 * BUF_T, wm, wn, lr, lc, acc);
    asm volatile("cp.async.wait_group 0;\n"); __syncthreads();
    mma_chunk(sbase + 3 * BUF_T, wm, wn, lr, lc, acc);

    // epilogue: bf16 hi/lo out
    const int ldc = (MODE == 1) ? 1024 : 2048;
    const int rb  = (MODE == 1) ? z * 2048 + bm : z * 1024 + bm;
#pragma unroll
    for (int nt = 0; nt < 4; nt++) {
        int col = bn + wn * 32 + nt * 8 + tig * 2;
#pragma unroll
        for (int mt = 0; mt < 4; mt++) {
            int row = rb + wm * 64 + mt * 16 + gid;
            __nv_bfloat16 h0, l0, h1, l1;
            split1(acc[mt][nt][0], h0, l0); split1(acc[mt][nt][1], h1, l1);
            *(__nv_bfloat162*)(Ch + (size_t)row * ldc + col) = __nv_bfloat162(h0, h1);
            *(__nv_bfloat162*)(Cl + (size_t)row * ldc + col) = __nv_bfloat162(l0, l1);
            split1(acc[mt][nt][2], h0, l0); split1(acc[mt][nt][3], h1, l1);
            *(__nv_bfloat162*)(Ch + (size_t)(row + 8) * ldc + col) = __nv_bfloat162(h0, h1);
            *(__nv_bfloat162*)(Cl + (size_t)(row + 8) * ldc + col) = __nv_bfloat162(l0, l1);
        }
    }
}

// ---------------------------------------------------------------------------
extern "C" void kernel_launch(void* const* d_in, const int* in_sizes, int n_in,
                              void* d_out, int out_size)
{
    const float* x  = (const float*)d_in[0];
    const float* Wq = (const float*)d_in[1];
    const float* bq = (const float*)d_in[2];
    const float* Wk = (const float*)d_in[3];
    const float* bk = (const float*)d_in[4];
    const float* Wv = (const float*)d_in[5];
    const float* bv = (const float*)d_in[6];
    const float* P  = (const float*)d_in[7];
    const float* Wo = (const float*)d_in[8];
    const float* bo = (const float*)d_in[9];
    float* out = (float*)d_out;

    __nv_bfloat16 *xh,*xl,*Woh,*Wol,*Wkvph,*Wkvpl,*WqTh,*WqTl;
    __nv_bfloat16 *Kpth,*Kptl,*Vpth,*Vptl,*Gh,*Gl,*ZTh,*ZTl,*attnh,*attnl;
    float *bkvp,*KVp,*cvec;
    cudaGetSymbolAddress((void**)&xh, g_xh);     cudaGetSymbolAddress((void**)&xl, g_xl);
    cudaGetSymbolAddress((void**)&Woh, g_Woh);   cudaGetSymbolAddress((void**)&Wol, g_Wol);
    cudaGetSymbolAddress((void**)&Wkvph, g_Wkvph); cudaGetSymbolAddress((void**)&Wkvpl, g_Wkvpl);
    cudaGetSymbolAddress((void**)&bkvp, g_bkvp);
    cudaGetSymbolAddress((void**)&WqTh, g_WqTh); cudaGetSymbolAddress((void**)&WqTl, g_WqTl);
    cudaGetSymbolAddress((void**)&KVp, g_KV);
    cudaGetSymbolAddress((void**)&Kpth, g_Kpth); cudaGetSymbolAddress((void**)&Kptl, g_Kptl);
    cudaGetSymbolAddress((void**)&Vpth, g_Vpth); cudaGetSymbolAddress((void**)&Vptl, g_Vptl);
    cudaGetSymbolAddress((void**)&cvec, g_c);
    cudaGetSymbolAddress((void**)&Gh, g_Gh);     cudaGetSymbolAddress((void**)&Gl, g_Gl);
    cudaGetSymbolAddress((void**)&ZTh, g_ZTh);   cudaGetSymbolAddress((void**)&ZTl, g_ZTl);
    cudaGetSymbolAddress((void**)&attnh, g_attnh); cudaGetSymbolAddress((void**)&attnl, g_attnl);

    cudaFuncSetAttribute(g5<0>, cudaFuncAttributeMaxDynamicSharedMemorySize, GSMEM);
    cudaFuncSetAttribute(g5<3>, cudaFuncAttributeMaxDynamicSharedMemorySize, GSMEM);
    cudaFuncSetAttribute(g5<4>, cudaFuncAttributeMaxDynamicSharedMemorySize, GSMEM);
    cudaFuncSetAttribute(g5k128<1>, cudaFuncAttributeMaxDynamicSharedMemorySize, GSMEM4);
    cudaFuncSetAttribute(g5k128<2>, cudaFuncAttributeMaxDynamicSharedMemorySize, GSMEM4);

    // pre-splits + weight prep
    split_kernel<<<(MTOT*ED/4 + 255)/256, 256>>>((const float4*)x, (uint2*)xh, (uint2*)xl, MTOT*ED/4);
    split_kernel<<<(ED*ED/4 + 255)/256, 256>>>((const float4*)Wo, (uint2*)Woh, (uint2*)Wol, ED*ED/4);
    fold_kernel<<<16, 256>>>(Wk, bk, Wv, bv, P, Wkvph, Wkvpl, bkvp);
    wq_trans<<<dim3(32, 4, 8), 256>>>(Wq, WqTh, WqTl);

    // KV projection: [8192,512]
    g5<0><<<dim3(NKV/128, MTOT/128), 256, GSMEM>>>(xh, xl, Wkvph, Wkvpl, bkvp, nullptr,
                                                   KVp, nullptr, nullptr);
    trans_kv<<<dim3(16, BD), 256>>>(KVp, Kpth, Kptl, Vpth, Vptl);
    c_kernel<<<BD, 256>>>(Kpth, Kptl, bq, cvec);

    // G[h] = Kpt_h @ WqT_h^T   (K=128, full prefetch)
    g5k128<1><<<dim3(8, 16, 8), 256, GSMEM4>>>(Kpth, Kptl, WqTh, WqTl, Gh, Gl);
    // ZT[h] = Wo_h @ Vpt_h^T   (K=128, full prefetch)
    g5k128<2><<<dim3(16, 8, 8), 256, GSMEM4>>>(Woh, Wol, Vpth, Vptl, ZTh, ZTl);

    // scores + softmax -> attn hi/lo
    g5<3><<<dim3(2, 64), 256, GSMEM>>>(xh, xl, Gh, Gl, nullptr, cvec,
                                       nullptr, attnh, attnl);
    // out = attn @ ZT + bo
    g5<4><<<dim3(8, 64), 256, GSMEM>>>(attnh, attnl, ZTh, ZTl, bo, nullptr,
                                       out, nullptr, nullptr);
}

// round 16
// speedup vs baseline: 1.0319x; 1.0319x over previous
#include <cuda_runtime.h>
#include <cuda_bf16.h>
#include <math.h>

// Problem dims (fixed by the reference)
#define BD 64
#define SD 128
#define ED 1024
#define HD_ 8
#define DH 128
#define KPD 32
#define MTOT (BD*SD)   // 8192
#define NKV 512

// Scratch (device globals — allocation-free rule)
__device__ __nv_bfloat16 g_xh  [MTOT*ED];
__device__ __nv_bfloat16 g_xl  [MTOT*ED];
__device__ __nv_bfloat16 g_Woh [ED*ED];
__device__ __nv_bfloat16 g_Wol [ED*ED];
__device__ __nv_bfloat16 g_Wkvph[NKV*ED];
__device__ __nv_bfloat16 g_Wkvpl[NKV*ED];
__device__ float         g_bkvp[NKV];
__device__ __nv_bfloat16 g_WqTh[ED*ED];
__device__ __nv_bfloat16 g_WqTl[ED*ED];
__device__ float         g_KV  [MTOT*NKV];
__device__ __nv_bfloat16 g_Kpth[16384*128];
__device__ __nv_bfloat16 g_Kptl[16384*128];
__device__ __nv_bfloat16 g_Vpth[16384*128];
__device__ __nv_bfloat16 g_Vptl[16384*128];
__device__ float         g_c   [BD*256];
__device__ __nv_bfloat16 g_Gh  [16384*1024];
__device__ __nv_bfloat16 g_Gl  [16384*1024];
__device__ __nv_bfloat16 g_ZTh [8*1024*2048];
__device__ __nv_bfloat16 g_ZTl [8*1024*2048];
__device__ __nv_bfloat16 g_attnh[MTOT*256];
__device__ __nv_bfloat16 g_attnl[MTOT*256];

// ---------------------------------------------------------------------------
// helpers
// ---------------------------------------------------------------------------
__device__ __forceinline__ unsigned smem_u32(const void* p) {
    unsigned a;
    asm("{ .reg .u64 t; cvta.to.shared.u64 t, %1; cvt.u32.u64 %0, t; }"
        : "=r"(a) : "l"(p));
    return a;
}
__device__ __forceinline__ void cp16(unsigned dst, const void* src) {
    asm volatile("cp.async.cg.shared.global [%0], [%1], 16;\n"
                 :: "r"(dst), "l"(src));
}
__device__ __forceinline__ void ldsm_x4(unsigned& r0, unsigned& r1,
                                        unsigned& r2, unsigned& r3, unsigned a) {
    asm volatile("ldmatrix.sync.aligned.m8n8.x4.shared.b16 {%0,%1,%2,%3}, [%4];\n"
                 : "=r"(r0), "=r"(r1), "=r"(r2), "=r"(r3) : "r"(a));
}
__device__ __forceinline__ void mma_bf16(
    float& c0, float& c1, float& c2, float& c3,
    unsigned a0, unsigned a1, unsigned a2, unsigned a3,
    unsigned b0, unsigned b1)
{
    asm volatile(
        "mma.sync.aligned.m16n8k16.row.col.f32.bf16.bf16.f32 "
        "{%0,%1,%2,%3}, {%4,%5,%6,%7}, {%8,%9}, {%0,%1,%2,%3};\n"
        : "+f"(c0), "+f"(c1), "+f"(c2), "+f"(c3)
        : "r"(a0), "r"(a1), "r"(a2), "r"(a3), "r"(b0), "r"(b1));
}
__device__ __forceinline__ void split1(float x, __nv_bfloat16& h, __nv_bfloat16& l) {
    h = __float2bfloat16_rn(x);
    l = __float2bfloat16_rn(x - __bfloat162float(h));
}

// ---------------------------------------------------------------------------
// fp32 -> bf16 hi/lo split
// ---------------------------------------------------------------------------
__global__ void __launch_bounds__(256) split_kernel(
    const float4* __restrict__ in, uint2* __restrict__ hi,
    uint2* __restrict__ lo, int n4)
{
    int i = blockIdx.x * blockDim.x + threadIdx.x;
    if (i >= n4) return;
    float4 v = in[i];
    __nv_bfloat16 h0,l0,h1,l1,h2,l2,h3,l3;
    split1(v.x,h0,l0); split1(v.y,h1,l1); split1(v.z,h2,l2); split1(v.w,h3,l3);
    __nv_bfloat162 ha(h0,h1), hb(h2,h3), la(l0,l1), lb(l2,l3);
    hi[i] = make_uint2(*(unsigned*)&ha, *(unsigned*)&hb);
    lo[i] = make_uint2(*(unsigned*)&la, *(unsigned*)&lb);
}

// ---------------------------------------------------------------------------
// Fold P into Wk / Wv; outputs bf16 hi/lo weights + fp32 bias
// ---------------------------------------------------------------------------
__global__ void __launch_bounds__(256) fold_kernel(
    const float* __restrict__ Wk, const float* __restrict__ bk,
    const float* __restrict__ Wv, const float* __restrict__ bv,
    const float* __restrict__ P,
    __nv_bfloat16* __restrict__ Wph, __nv_bfloat16* __restrict__ Wpl,
    float* __restrict__ bkvp)
{
    const int blk = blockIdx.x;
    const int kv = blk >> 3, h = blk & 7;
    const float* Wsrc = kv ? Wv : Wk;
    const float* bsrc = kv ? bv : bk;

    __shared__ float Ps[128][32];
    const int tid = threadIdx.x;
#pragma unroll
    for (int u = 0; u < 16; u++) {
        int e = tid + 256 * u;
        Ps[e >> 5][e & 31] = P[e];
    }
    __syncthreads();

    if (tid < 32) {
        float s = 0.f;
#pragma unroll 4
        for (int d = 0; d < 128; d++) s = fmaf(Ps[d][tid], bsrc[h * 128 + d], s);
        bkvp[kv * 256 + h * 32 + tid] = s;
    }

    for (int fc = 0; fc < 4; fc++) {
        const int f = fc * 256 + tid;
        float acc[32];
#pragma unroll
        for (int i = 0; i < 32; i++) acc[i] = 0.f;
        for (int d = 0; d < 128; d++) {
            float w = Wsrc[(size_t)(h * 128 + d) * ED + f];
#pragma unroll
            for (int i = 0; i < 32; i++) acc[i] = fmaf(Ps[d][i], w, acc[i]);
        }
#pragma unroll
        for (int i = 0; i < 32; i++) {
            __nv_bfloat16 hh, ll;
            split1(acc[i], hh, ll);
            size_t idx = (size_t)(kv * 256 + h * 32 + i) * ED + f;
            Wph[idx] = hh; Wpl[idx] = ll;
        }
    }
}

// ---------------------------------------------------------------------------
// Wq transpose -> bf16 hi/lo  WqT[(h*1024+e)*128 + t]
// ---------------------------------------------------------------------------
__global__ void __launch_bounds__(256) wq_trans(
    const float* __restrict__ Wq,
    __nv_bfloat16* __restrict__ Th, __nv_bfloat16* __restrict__ Tl)
{
    __shared__ float tile[32][33];
    const int h  = blockIdx.z;
    const int e0 = blockIdx.x * 32;
    const int t0 = blockIdx.y * 32;
    const int tx = threadIdx.x & 31;
    const int ty = threadIdx.x >> 5;
#pragma unroll
    for (int r = 0; r < 4; r++) {
        int tl = ty + r * 8;
        tile[tl][tx] = Wq[(size_t)(h * 128 + t0 + tl) * ED + e0 + tx];
    }
    __syncthreads();
#pragma unroll
    for (int r = 0; r < 4; r++) {
        int el = ty + r * 8;
        __nv_bfloat16 hh, ll;
        split1(tile[tx][el], hh, ll);
        size_t idx = (size_t)(h * 1024 + e0 + el) * 128 + t0 + tx;
        Th[idx] = hh; Tl[idx] = ll;
    }
}

// ---------------------------------------------------------------------------
// Transpose KVp -> Kpt/Vpt [h][b][j][t], bf16 hi/lo
// ---------------------------------------------------------------------------
__global__ void __launch_bounds__(256) trans_kv(
    const float* __restrict__ KVp,
    __nv_bfloat16* __restrict__ Kh, __nv_bfloat16* __restrict__ Kl,
    __nv_bfloat16* __restrict__ Vh, __nv_bfloat16* __restrict__ Vl)
{
    __shared__ float tile[32][129];
    const int cc = blockIdx.x;
    const int b  = blockIdx.y;
    const int tid = threadIdx.x;
#pragma unroll
    for (int u = 0; u < 16; u++) {
        int idx = tid + 256 * u;
        int t = idx >> 5, c = idx & 31;
        tile[c][t] = KVp[((size_t)b * 128 + t) * NKV + cc * 32 + c];
    }
    __syncthreads();
#pragma unroll
    for (int u = 0; u < 16; u++) {
        int idx = tid + 256 * u;
        int c = idx >> 7, t = idx & 127;
        int col = cc * 32 + c;
        __nv_bfloat16 hh, ll;
        split1(tile[c][t], hh, ll);
        if (col < 256) {
            int h = col >> 5, j = col & 31;
            size_t o = ((size_t)(h * 64 + b) * 32 + j) * 128 + t;
            Kh[o] = hh; Kl[o] = ll;
        } else {
            int c2 = col - 256;
            int h = c2 >> 5, j = c2 & 31;
            size_t o = ((size_t)(h * 64 + b) * 32 + j) * 128 + t;
            Vh[o] = hh; Vl[o] = ll;
        }
    }
}

// ---------------------------------------------------------------------------
// c[b][h*32+j] = sum_t Kpt[h,b,j,t] * bq[h*128+t]   (reads hi+lo)
// ---------------------------------------------------------------------------
__global__ void __launch_bounds__(256) c_kernel(
    const __nv_bfloat16* __restrict__ Kh, const __nv_bfloat16* __restrict__ Kl,
    const float* __restrict__ bq, float* __restrict__ cvec)
{
    const int b = blockIdx.x, hj = threadIdx.x;
    const int h = hj >> 5, j = hj & 31;
    const size_t base = ((size_t)(h * 64 + b) * 32 + j) * 128;
    const float* bqh = bq + h * 128;
    float s = 0.f;
#pragma unroll 4
    for (int t = 0; t < 128; t++)
        s = fmaf(__bfloat162float(Kh[base + t]) + __bfloat162float(Kl[base + t]),
                 __ldg(bqh + t), s);
    cvec[b * 256 + hj] = s;
}

// ---------------------------------------------------------------------------
// Unified pipelined GEMM core, bf16x3 emulation (round-8 structure; MMA issue
// order changed: products outermost so consecutive MMAs hit different
// accumulators — breaks the per-acc RAW chain).
// MODE 0: KVp = x @ Wkvp^T + bkvp            (K=1024, fp32 out, ldc 512)
// MODE 1: G[z] = Kpt_z @ WqT_z^T             (K=128,  bf16 hi/lo out, ldc 1024)
// MODE 2: ZT[z] = Wo(:, z*128:+128) @ Vpt_z^T (K=128, bf16 hi/lo out, ldc 2048)
// MODE 3: attn = softmax((x@G^T + c)*scale)  (K=1024, bf16 hi/lo out, ldc 256)
// MODE 4: out = attn @ ZT + bo               (K=256,  fp32 out, ldc 1024)
// ---------------------------------------------------------------------------
#define AROW 80
#define TILE_T (128*AROW)
#define BUF_T (4*TILE_T)     // 40960
#define GSMEM (2*BUF_T)      // 81920

template<int MODE>
__device__ __forceinline__ void stage_g5(
    unsigned dbase, int tid, int bm, int bn, int z, int b, int k0,
    const __nv_bfloat16* __restrict__ Ah, const __nv_bfloat16* __restrict__ Al,
    const __nv_bfloat16* __restrict__ Bh, const __nv_bfloat16* __restrict__ Bl)
{
#pragma unroll
    for (int idx = tid; idx < 512; idx += 256) {
        int row = idx >> 2, c16 = idx & 3;
        size_t off;
        if (MODE == 0 || MODE == 3)
            off = (size_t)(bm + row) * 1024 + k0 + c16 * 8;
        else if (MODE == 1)
            off = ((size_t)z * 2048 + bm + row) * 128 + k0 + c16 * 8;
        else if (MODE == 2)
            off = (size_t)(bm + row) * 1024 + z * 128 + k0 + c16 * 8;
        else
            off = (size_t)(bm + row) * 256 + k0 + c16 * 8;
        unsigned d = dbase + row * AROW + c16 * 16;
        cp16(d, Ah + off);
        cp16(d + TILE_T, Al + off);
    }
#pragma unroll
    for (int idx = tid; idx < 512; idx += 256) {
        int row = idx >> 2, c16 = idx & 3;
        size_t off;
        if (MODE == 0)
            off = (size_t)(bn + row) * 1024 + k0 + c16 * 8;
        else if (MODE == 1)
            off = ((size_t)z * 1024 + bn + row) * 128 + k0 + c16 * 8;
        else if (MODE == 2)
            off = ((size_t)z * 2048 + bn + row) * 128 + k0 + c16 * 8;
        else if (MODE == 3) {
            int nc = bn + row;
            off = ((size_t)(nc >> 5) * 2048 + b * 32 + (nc & 31)) * 1024 + k0 + c16 * 8;
        } else {
            int kc = k0 >> 5;
            off = (size_t)kc * (1024 * 2048) + (size_t)(bn + row) * 2048 + b * 32 + c16 * 8;
        }
        unsigned d = dbase + 2 * TILE_T + row * AROW + c16 * 16;
        cp16(d, Bh + off);
        cp16(d + TILE_T, Bl + off);
    }
}

template<int MODE>
__global__ void __launch_bounds__(256, 2) g5(
    const __nv_bfloat16* __restrict__ Ah, const __nv_bfloat16* __restrict__ Al,
    const __nv_bfloat16* __restrict__ Bh, const __nv_bfloat16* __restrict__ Bl,
    const float* __restrict__ bias, const float* __restrict__ cvec,
    float* __restrict__ Cf,
    __nv_bfloat16* __restrict__ Ch, __nv_bfloat16* __restrict__ Cl)
{
    constexpr int KTOT = (MODE == 1 || MODE == 2) ? 128 : (MODE == 4 ? 256 : 1024);
    constexpr int NS   = KTOT / 32;

    extern __shared__ char smem[];
    const unsigned sbase = smem_u32(smem);

    const int tid  = threadIdx.x;
    const int lane = tid & 31;
    const int w    = tid >> 5;
    const int wm   = w >> 2, wn = w & 3;
    const int gid  = lane >> 2, tig = lane & 3;
    const int lr   = lane & 15;
    const int lc   = (lane >> 4) * 16;

    const int bm = blockIdx.y * 128;
    const int bn = blockIdx.x * 128;
    const int z  = blockIdx.z;
    const int b  = blockIdx.y;

    float acc[4][4][4];
#pragma unroll
    for (int mt = 0; mt < 4; mt++)
#pragma unroll
        for (int nt = 0; nt < 4; nt++)
#pragma unroll
            for (int i = 0; i < 4; i++) acc[mt][nt][i] = 0.f;

    stage_g5<MODE>(sbase, tid, bm, bn, z, b, 0, Ah, Al, Bh, Bl);
    asm volatile("cp.async.commit_group;\n");

    int buf = 0;
    for (int s = 0; s < NS; s++) {
        if (s + 1 < NS) {
            stage_g5<MODE>(sbase + (buf ^ 1) * BUF_T, tid, bm, bn, z, b,
                           (s + 1) * 32, Ah, Al, Bh, Bl);
            asm volatile("cp.async.commit_group;\n");
            asm volatile("cp.async.wait_group 1;\n");
        } else {
            asm volatile("cp.async.wait_group 0;\n");
        }
        __syncthreads();

        const unsigned bAh = sbase + buf * BUF_T;
        const unsigned bAl = bAh + TILE_T;
        const unsigned bBh = bAh + 2 * TILE_T;
        const unsigned bBl = bBh + TILE_T;

#pragma unroll
        for (int kk = 0; kk < 2; kk++) {
            const int kb = kk * 32 + lc;
            unsigned bfh[4][2], bfl[4][2];
#pragma unroll
            for (int np = 0; np < 2; np++) {
                const int n0 = wn * 32 + np * 16;
                unsigned r0, r1, r2, r3;
                ldsm_x4(r0, r1, r2, r3, bBh + (n0 + lr) * AROW + kb);
                bfh[np*2][0] = r0; bfh[np*2+1][0] = r1;
                bfh[np*2][1] = r2; bfh[np*2+1][1] = r3;
                ldsm_x4(r0, r1, r2, r3, bBl + (n0 + lr) * AROW + kb);
                bfl[np*2][0] = r0; bfl[np*2+1][0] = r1;
                bfl[np*2][1] = r2; bfl[np*2+1][1] = r3;
            }
#pragma unroll
            for (int mt = 0; mt < 4; mt++) {
                const int m0 = wm * 64 + mt * 16;
                unsigned aH[4], aL[4];
                ldsm_x4(aH[0], aH[1], aH[2], aH[3], bAh + (m0 + lr) * AROW + kb);
                ldsm_x4(aL[0], aL[1], aL[2], aL[3], bAl + (m0 + lr) * AROW + kb);
                // products outermost: consecutive MMAs hit different accs
                // (per-acc add order per k-step stays HH -> HL -> LH:
                //  bit-identical arithmetic to round 8)
#pragma unroll
                for (int nt = 0; nt < 4; nt++)
                    mma_bf16(acc[mt][nt][0], acc[mt][nt][1],
                             acc[mt][nt][2], acc[mt][nt][3],
                             aH[0], aH[1], aH[2], aH[3],
                             bfh[nt][0], bfh[nt][1]);
#pragma unroll
                for (int nt = 0; nt < 4; nt++)
                    mma_bf16(acc[mt][nt][0], acc[mt][nt][1],
                             acc[mt][nt][2], acc[mt][nt][3],
                             aH[0], aH[1], aH[2], aH[3],
                             bfl[nt][0], bfl[nt][1]);
#pragma unroll
                for (int nt = 0; nt < 4; nt++)
                    mma_bf16(acc[mt][nt][0], acc[mt][nt][1],
                             acc[mt][nt][2], acc[mt][nt][3],
                             aL[0], aL[1], aL[2], aL[3],
                             bfh[nt][0], bfh[nt][1]);
            }
        }
        __syncthreads();
        buf ^= 1;
    }

    // ------------------ epilogues ------------------
    if (MODE == 0 || MODE == 4) {
        const int ldc = (MODE == 0) ? 512 : 1024;
        const int rb  = (MODE == 0) ? bm : b * 128;
#pragma unroll
        for (int nt = 0; nt < 4; nt++) {
            int col = bn + wn * 32 + nt * 8 + tig * 2;
            float bb0 = __ldg(bias + col), bb1 = __ldg(bias + col + 1);
#pragma unroll
            for (int mt = 0; mt < 4; mt++) {
                int row = rb + wm * 64 + mt * 16 + gid;
                *(float2*)(Cf + (size_t)row * ldc + col) =
                    make_float2(acc[mt][nt][0] + bb0, acc[mt][nt][1] + bb1);
                *(float2*)(Cf + (size_t)(row + 8) * ldc + col) =
                    make_float2(acc[mt][nt][2] + bb0, acc[mt][nt][3] + bb1);
            }
        }
    } else if (MODE == 1 || MODE == 2) {
        const int ldc = (MODE == 1) ? 1024 : 2048;
        const int rb  = (MODE == 1) ? z * 2048 + bm : z * 1024 + bm;
#pragma unroll
        for (int nt = 0; nt < 4; nt++) {
            int col = bn + wn * 32 + nt * 8 + tig * 2;
#pragma unroll
            for (int mt = 0; mt < 4; mt++) {
                int row = rb + wm * 64 + mt * 16 + gid;
                __nv_bfloat16 h0, l0, h1, l1;
                split1(acc[mt][nt][0], h0, l0); split1(acc[mt][nt][1], h1, l1);
                *(__nv_bfloat162*)(Ch + (size_t)row * ldc + col) = __nv_bfloat162(h0, h1);
                *(__nv_bfloat162*)(Cl + (size_t)row * ldc + col) = __nv_bfloat162(l0, l1);
                split1(acc[mt][nt][2], h0, l0); split1(acc[mt][nt][3], h1, l1);
                *(__nv_bfloat162*)(Ch + (size_t)(row + 8) * ldc + col) = __nv_bfloat162(h0, h1);
                *(__nv_bfloat162*)(Cl + (size_t)(row + 8) * ldc + col) = __nv_bfloat162(l0, l1);
            }
        }
    } else {   // MODE 3: +c, scale, softmax per (row, 32-col h-group), bf16 hi/lo out
        const float scale = 0.08838834764831845f;
        float cA[4], cB[4];
#pragma unroll
        for (int nt = 0; nt < 4; nt++) {
            int col = bn + wn * 32 + nt * 8 + tig * 2;
            cA[nt] = __ldg(cvec + b * 256 + col);
            cB[nt] = __ldg(cvec + b * 256 + col + 1);
        }
#pragma unroll
        for (int mt = 0; mt < 4; mt++)
#pragma unroll
            for (int nt = 0; nt < 4; nt++) {
                acc[mt][nt][0] = (acc[mt][nt][0] + cA[nt]) * scale;
                acc[mt][nt][1] = (acc[mt][nt][1] + cB[nt]) * scale;
                acc[mt][nt][2] = (acc[mt][nt][2] + cA[nt]) * scale;
                acc[mt][nt][3] = (acc[mt][nt][3] + cB[nt]) * scale;
            }
#pragma unroll
        for (int mt = 0; mt < 4; mt++) {
            float m0 = -1e30f, m1 = -1e30f;
#pragma unroll
            for (int nt = 0; nt < 4; nt++) {
                m0 = fmaxf(m0, fmaxf(acc[mt][nt][0], acc[mt][nt][1]));
                m1 = fmaxf(m1, fmaxf(acc[mt][nt][2], acc[mt][nt][3]));
            }
            m0 = fmaxf(m0, __shfl_xor_sync(0xffffffffu, m0, 1));
            m0 = fmaxf(m0, __shfl_xor_sync(0xffffffffu, m0, 2));
            m1 = fmaxf(m1, __shfl_xor_sync(0xffffffffu, m1, 1));
            m1 = fmaxf(m1, __shfl_xor_sync(0xffffffffu, m1, 2));
            float s0 = 0.f, s1 = 0.f;
#pragma unroll
            for (int nt = 0; nt < 4; nt++) {
                acc[mt][nt][0] = expf(acc[mt][nt][0] - m0);
                acc[mt][nt][1] = expf(acc[mt][nt][1] - m0);
                acc[mt][nt][2] = expf(acc[mt][nt][2] - m1);
                acc[mt][nt][3] = expf(acc[mt][nt][3] - m1);
                s0 += acc[mt][nt][0] + acc[mt][nt][1];
                s1 += acc[mt][nt][2] + acc[mt][nt][3];
            }
            s0 += __shfl_xor_sync(0xffffffffu, s0, 1);
            s0 += __shfl_xor_sync(0xffffffffu, s0, 2);
            s1 += __shfl_xor_sync(0xffffffffu, s1, 1);
            s1 += __shfl_xor_sync(0xffffffffu, s1, 2);
            float i0 = 1.f / s0, i1 = 1.f / s1;
#pragma unroll
            for (int nt = 0; nt < 4; nt++) {
                acc[mt][nt][0] *= i0; acc[mt][nt][1] *= i0;
                acc[mt][nt][2] *= i1; acc[mt][nt][3] *= i1;
            }
        }
#pragma unroll
        for (int nt = 0; nt < 4; nt++) {
            int col = bn + wn * 32 + nt * 8 + tig * 2;
#pragma unroll
            for (int mt = 0; mt < 4; mt++) {
                size_t row = (size_t)bm + wm * 64 + mt * 16 + gid;
                __nv_bfloat16 h0, l0, h1, l1;
                split1(acc[mt][nt][0], h0, l0); split1(acc[mt][nt][1], h1, l1);
                *(__nv_bfloat162*)(Ch + row * 256 + col) = __nv_bfloat162(h0, h1);
                *(__nv_bfloat162*)(Cl + row * 256 + col) = __nv_bfloat162(l0, l1);
                split1(acc[mt][nt][2], h0, l0); split1(acc[mt][nt][3], h1, l1);
                *(__nv_bfloat162*)(Ch + (row + 8) * 256 + col) = __nv_bfloat162(h0, h1);
                *(__nv_bfloat162*)(Cl + (row + 8) * 256 + col) = __nv_bfloat162(l0, l1);
            }
        }
    }
}

// ---------------------------------------------------------------------------
extern "C" void kernel_launch(void* const* d_in, const int* in_sizes, int n_in,
                              void* d_out, int out_size)
{
    const float* x  = (const float*)d_in[0];
    const float* Wq = (const float*)d_in[1];
    const float* bq = (const float*)d_in[2];
    const float* Wk = (const float*)d_in[3];
    const float* bk = (const float*)d_in[4];
    const float* Wv = (const float*)d_in[5];
    const float* bv = (const float*)d_in[6];
    const float* P  = (const float*)d_in[7];
    const float* Wo = (const float*)d_in[8];
    const float* bo = (const float*)d_in[9];
    float* out = (float*)d_out;

    __nv_bfloat16 *xh,*xl,*Woh,*Wol,*Wkvph,*Wkvpl,*WqTh,*WqTl;
    __nv_bfloat16 *Kpth,*Kptl,*Vpth,*Vptl,*Gh,*Gl,*ZTh,*ZTl,*attnh,*attnl;
    float *bkvp,*KVp,*cvec;
    cudaGetSymbolAddress((void**)&xh, g_xh);     cudaGetSymbolAddress((void**)&xl, g_xl);
    cudaGetSymbolAddress((void**)&Woh, g_Woh);   cudaGetSymbolAddress((void**)&Wol, g_Wol);
    cudaGetSymbolAddress((void**)&Wkvph, g_Wkvph); cudaGetSymbolAddress((void**)&Wkvpl, g_Wkvpl);
    cudaGetSymbolAddress((void**)&bkvp, g_bkvp);
    cudaGetSymbolAddress((void**)&WqTh, g_WqTh); cudaGetSymbolAddress((void**)&WqTl, g_WqTl);
    cudaGetSymbolAddress((void**)&KVp, g_KV);
    cudaGetSymbolAddress((void**)&Kpth, g_Kpth); cudaGetSymbolAddress((void**)&Kptl, g_Kptl);
    cudaGetSymbolAddress((void**)&Vpth, g_Vpth); cudaGetSymbolAddress((void**)&Vptl, g_Vptl);
    cudaGetSymbolAddress((void**)&cvec, g_c);
    cudaGetSymbolAddress((void**)&Gh, g_Gh);     cudaGetSymbolAddress((void**)&Gl, g_Gl);
    cudaGetSymbolAddress((void**)&ZTh, g_ZTh);   cudaGetSymbolAddress((void**)&ZTl, g_ZTl);
    cudaGetSymbolAddress((void**)&attnh, g_attnh); cudaGetSymbolAddress((void**)&attnl, g_attnl);

    cudaFuncSetAttribute(g5<0>, cudaFuncAttributeMaxDynamicSharedMemorySize, GSMEM);
    cudaFuncSetAttribute(g5<1>, cudaFuncAttributeMaxDynamicSharedMemorySize, GSMEM);
    cudaFuncSetAttribute(g5<2>, cudaFuncAttributeMaxDynamicSharedMemorySize, GSMEM);
    cudaFuncSetAttribute(g5<3>, cudaFuncAttributeMaxDynamicSharedMemorySize, GSMEM);
    cudaFuncSetAttribute(g5<4>, cudaFuncAttributeMaxDynamicSharedMemorySize, GSMEM);

    // pre-splits + weight prep
    split_kernel<<<(MTOT*ED/4 + 255)/256, 256>>>((const float4*)x, (uint2*)xh, (uint2*)xl, MTOT*ED/4);
    split_kernel<<<(ED*ED/4 + 255)/256, 256>>>((const float4*)Wo, (uint2*)Woh, (uint2*)Wol, ED*ED/4);
    fold_kernel<<<16, 256>>>(Wk, bk, Wv, bv, P, Wkvph, Wkvpl, bkvp);
    wq_trans<<<dim3(32, 4, 8), 256>>>(Wq, WqTh, WqTl);

    // KV projection: [8192,512]
    g5<0><<<dim3(NKV/128, MTOT/128), 256, GSMEM>>>(xh, xl, Wkvph, Wkvpl, bkvp, nullptr,
                                                   KVp, nullptr, nullptr);
    trans_kv<<<dim3(16, BD), 256>>>(KVp, Kpth, Kptl, Vpth, Vptl);
    c_kernel<<<BD, 256>>>(Kpth, Kptl, bq, cvec);

    // G[h] = Kpt_h @ WqT_h^T   (M=2048, N=1024, K=128)
    g5<1><<<dim3(8, 16, 8), 256, GSMEM>>>(Kpth, Kptl, WqTh, WqTl, nullptr, nullptr,
                                          nullptr, Gh, Gl);
    // ZT[h] = Wo_h @ Vpt_h^T   (M=1024, N=2048, K=128)
    g5<2><<<dim3(16, 8, 8), 256, GSMEM>>>(Woh, Wol, Vpth, Vptl, nullptr, nullptr,
                                          nullptr, ZTh, ZTl);
    // scores + softmax -> attn hi/lo
    g5<3><<<dim3(2, 64), 256, GSMEM>>>(xh, xl, Gh, Gl, nullptr, cvec,
                                       nullptr, attnh, attnl);
    // out = attn @ ZT + bo
    g5<4><<<dim3(8, 64), 256, GSMEM>>>(attnh, attnl, ZTh, ZTl, bo, nullptr,
                                       out, nullptr, nullptr);
}